// round 7
// baseline (speedup 1.0000x reference)
#include <cuda_runtime.h>
#include <math.h>
#include <stdint.h>

#define Bb 16
#define Cc 32
#define Hh 128
#define Ww 128
#define HW 16384
#define Rr 8
#define OUTC 32

typedef unsigned long long ull;

// ---------------- scratch (device globals; no allocation) ----------------
__device__ __align__(16) float d_kern[Bb * Rr * 288 * 32];   // [b][r][c*9+kl][oo]
__device__ float          d_pool[Bb * Cc * 9];               // [b][c][kl]
__device__ float          d_gate[Bb * 576];                  // [b][rr*9+kl]
__device__ int            d_sync[Bb];                        // pool->gate tickets (reset each run)
__device__ __align__(16) float d_int[(size_t)Bb * HW * 32];  // channel-inner input [b][pix][c]
__device__ unsigned char  d_sel[Bb * HW];                    // r1 | r2<<3
__device__ int            d_segcnt[Bb * Rr * 64];
__device__ int            d_cnt[Bb * Rr];
__device__ unsigned short d_list[Bb * Rr * HW];              // pix | flags<<14 (sorted by pix)
__device__ __align__(16) float d_cat[(size_t)Bb * 64 * HW];  // CHANNEL-FIRST [b][ch][pix]
__device__ __align__(16) float d_wft[9 * 64 * 32];           // [kl][ch][o]

// ---------------- f32x2 helpers ----------------
__device__ __forceinline__ ull pack2(float v) {
    ull r; asm("mov.b64 %0, {%1, %1};" : "=l"(r) : "f"(v)); return r;
}
__device__ __forceinline__ ull ffma2(ull a, ull b, ull c) {
    ull d; asm("fma.rn.f32x2 %0, %1, %2, %3;" : "=l"(d) : "l"(a), "l"(b), "l"(c)); return d;
}

// ---------------- L1: pool (512 blocks) + gate (last block per b) ----------------
__global__ void __launch_bounds__(128) poolgate_kernel(
    const float* __restrict__ in,
    const float* __restrict__ w1, const float* __restrict__ b1) {
    int bc = blockIdx.x;
    int b = bc >> 5;
    int x = threadIdx.x;
    const float* img = in + (size_t)bc * HW;
    float rb0 = 0.f, rb1 = 0.f, rb2 = 0.f;
    #pragma unroll 4
    for (int yy = 0; yy < Hh; yy++) {
        float v = __ldg(img + yy * Ww + x);
        if (yy < 43) rb0 += v;
        if (yy >= 42 && yy < 86) rb1 += v;
        if (yy >= 85) rb2 += v;
    }
    __shared__ float srow[3][128];
    srow[0][x] = rb0; srow[1][x] = rb1; srow[2][x] = rb2;
    __syncthreads();
    if (x < 9) {
        int i = x / 3, j = x % 3;
        const int s[3] = {0, 42, 85}, e[3] = {43, 86, 128};
        const int span[3] = {43, 44, 43};
        float ssum = 0.f;
        for (int xx = s[j]; xx < e[j]; xx++) ssum += srow[i][xx];
        d_pool[bc * 9 + x] = ssum / (float)(span[i] * span[j]);
    }
    // ---- ticket: last block of this b computes the gate ----
    __syncthreads();
    __threadfence();
    __syncthreads();
    __shared__ int winner;
    if (x == 0) {
        int tk = atomicAdd(&d_sync[b], 1);
        winner = (tk == 31);
    }
    __syncthreads();
    if (winner) {
        __threadfence();
        for (int i = x; i < 576; i += 128) {
            int rr = i / 9, kl = i % 9;
            float s = __ldg(b1 + rr);
            #pragma unroll
            for (int c2 = 0; c2 < Cc; c2++)
                s += d_pool[(b * Cc + c2) * 9 + kl] * __ldg(w1 + rr * Cc + c2);
            d_gate[b * 576 + i] = 1.f / (1.f + expf(-s));
        }
        __syncthreads();
        if (x == 0) d_sync[b] = 0;   // reset for next graph replay
    }
}

// ---------------- L2: MEGA — kern gen | transpose | s1 select | wft ----------------
#define MEGA_KERN   4608
#define MEGA_TRANS  8192
#define MEGA_S1     1024
#define MEGA_WFT    72

__global__ void __launch_bounds__(256) mega_kernel(
    const float* __restrict__ in, const float* __restrict__ guide,
    const float* __restrict__ w2, const float* __restrict__ b2,
    const float* __restrict__ w_spa, const float* __restrict__ b_spa,
    const float* __restrict__ w_spec, const float* __restrict__ b_spec,
    const float* __restrict__ w_f) {
    int blk = blockIdx.x;
    int t = threadIdx.x;
    __shared__ float tt[32][33];
    __shared__ int scnt[Rr];

    if (blk < MEGA_KERN) {
        // ---- dynamic kernel generation ----
        int idx = blk * 256 + t;
        int oo = idx & 31;
        int ckl = (idx >> 5) % 288;
        int t2 = idx / (288 * 32);
        int r = t2 & 7;
        int b = t2 >> 3;
        int c = ckl / 9, kl = ckl % 9;
        int jj = r * 1024 + oo * 32 + c;
        float v = __ldg(b2 + jj);
        float4 wa = __ldg((const float4*)(w2 + jj * 8));
        float4 wb = __ldg((const float4*)(w2 + jj * 8 + 4));
        const float* gb = d_gate + b * 576 + r * 72 + kl;
        v += gb[0]  * wa.x + gb[9]  * wa.y + gb[18] * wa.z + gb[27] * wa.w;
        v += gb[36] * wb.x + gb[45] * wb.y + gb[54] * wb.z + gb[63] * wb.w;
        d_kern[idx] = v;
    } else if (blk < MEGA_KERN + MEGA_TRANS) {
        // ---- input transpose -> d_int[b][pix][c] ----
        int tb = blk - MEGA_KERN;
        int px0 = (tb & 511) * 32;
        int b = tb >> 9;
        int lane = t & 31, wr = t >> 5;
        #pragma unroll
        for (int i = 0; i < 4; i++) {
            int c = wr + i * 8;
            tt[c][lane] = __ldg(in + ((size_t)(b * Cc + c)) * HW + px0 + lane);
        }
        __syncthreads();
        #pragma unroll
        for (int i = 0; i < 4; i++) {
            int pr = wr + i * 8;
            d_int[((size_t)b * HW + px0 + pr) * 32 + lane] = tt[lane][pr];
        }
    } else if (blk < MEGA_KERN + MEGA_TRANS + MEGA_S1) {
        // ---- s1: argmax select + per-segment counts ----
        int sb = blk - (MEGA_KERN + MEGA_TRANS);
        int seg = sb & 63;
        int b = sb >> 6;
        int pix = seg * 256 + t;

        float gv[Cc];
        #pragma unroll
        for (int c = 0; c < Cc; c++)
            gv[c] = __ldg(guide + ((size_t)(b * Cc + c)) * HW + pix);

        float best1 = -1e30f, best2 = -1e30f;
        int r1 = 0, r2 = 0;
        for (int r = 0; r < Rr; r++) {
            float s1 = __ldg(b_spa + r), s2 = __ldg(b_spec + r);
            #pragma unroll
            for (int c = 0; c < Cc; c++) {
                s1 += gv[c] * __ldg(w_spa + r * Cc + c);
                s2 += gv[c] * __ldg(w_spec + r * Cc + c);
            }
            if (s1 > best1) { best1 = s1; r1 = r; }
            if (s2 > best2) { best2 = s2; r2 = r; }
        }
        d_sel[b * HW + pix] = (unsigned char)(r1 | (r2 << 3));

        if (t < Rr) scnt[t] = 0;
        __syncthreads();
        if (r1 == r2) atomicAdd(&scnt[r1], 1);
        else { atomicAdd(&scnt[r1], 1); atomicAdd(&scnt[r2], 1); }
        __syncthreads();
        if (t < Rr) d_segcnt[(b * Rr + t) * 64 + seg] = scnt[t];
    } else {
        // ---- fusion weight transpose: wft[kl][ch][o] ----
        int wb2 = blk - (MEGA_KERN + MEGA_TRANS + MEGA_S1);
        int idx = wb2 * 256 + t;
        int o = idx & 31, ch = (idx >> 5) & 63, kl = idx >> 11;
        d_wft[idx] = w_f[(o * 64 + ch) * 9 + kl];
    }
}

// ---------------- L3: s3 emit with inline segment scan (replaces s2+s3) ----------------
__global__ void __launch_bounds__(256) s3_emit_kernel() {
    int t = threadIdx.x, seg = blockIdx.x, b = blockIdx.y;
    int w = t >> 5, lane = t & 31;

    // warp w == region r: scan its 64 segment counts
    __shared__ int sbase[Rr];
    {
        int r = w;
        const int* row = d_segcnt + (b * Rr + r) * 64;
        int c0 = row[lane], c1 = row[32 + lane];
        int is0 = c0, is1 = c1;
        #pragma unroll
        for (int o = 1; o < 32; o <<= 1) {
            int v0 = __shfl_up_sync(0xFFFFFFFFu, is0, o);
            int v1 = __shfl_up_sync(0xFFFFFFFFu, is1, o);
            if (lane >= o) { is0 += v0; is1 += v1; }
        }
        int total0 = __shfl_sync(0xFFFFFFFFu, is0, 31);
        is1 += total0;
        int excl;
        if (seg == 0) excl = 0;
        else if (seg <= 32) excl = __shfl_sync(0xFFFFFFFFu, is0, seg - 1);
        else excl = __shfl_sync(0xFFFFFFFFu, is1, seg - 33);
        if (lane == 0) sbase[r] = excl;
        if (seg == 63 && lane == 31) d_cnt[b * Rr + r] = is1;
    }
    __syncthreads();

    int pix = seg * 256 + t;
    int sel = d_sel[b * HW + pix];
    int r1 = sel & 7, r2 = sel >> 3;

    __shared__ int wcnt[8][8];
    int rank1 = 0, rank2 = 0;
    unsigned ltm = (1u << lane) - 1u;
    #pragma unroll
    for (int r = 0; r < Rr; r++) {
        unsigned m = __ballot_sync(0xFFFFFFFFu, (r1 == r) || (r2 == r));
        if (lane == 0) wcnt[w][r] = __popc(m);
        if (r1 == r) rank1 = __popc(m & ltm);
        if (r2 == r) rank2 = __popc(m & ltm);
    }
    __syncthreads();
    int wb1 = 0, wb2 = 0;
    for (int w2 = 0; w2 < w; w2++) { wb1 += wcnt[w2][r1]; wb2 += wcnt[w2][r2]; }

    unsigned short pv = (unsigned short)pix;
    if (r1 == r2) {
        int off = sbase[r1] + wb1 + rank1;
        d_list[(b * Rr + r1) * HW + off] = (unsigned short)(pv | (3u << 14));
    } else {
        int off1 = sbase[r1] + wb1 + rank1;
        d_list[(b * Rr + r1) * HW + off1] = (unsigned short)(pv | (1u << 14));
        int off2 = sbase[r2] + wb2 + rank2;
        d_list[(b * Rr + r2) * HW + off2] = (unsigned short)(pv | (2u << 14));
    }
}

// ---------------- L4: dynconv (512 entries/block, slab loaded once) ----------------
__global__ void __launch_bounds__(256) dynconv_kernel() {
    int b = blockIdx.z, r = blockIdx.y;
    int cnt = d_cnt[b * Rr + r];
    if (blockIdx.x * 512 >= cnt) return;

    __shared__ __align__(16) float ks[288 * 32];   // [c*9+tap][oo]
    {
        const float4* kg = (const float4*)(d_kern + (size_t)(b * Rr + r) * 9216);
        float4* kd = (float4*)ks;
        #pragma unroll
        for (int i = 0; i < 9; i++) kd[threadIdx.x + 256 * i] = kg[threadIdx.x + 256 * i];
    }
    __syncthreads();

    int w = threadIdx.x >> 5, lane = threadIdx.x & 31;
    int p = lane & 15, gg = lane >> 4;     // gg selects oo half (16 oo)
    const unsigned short* lst = d_list + (b * Rr + r) * HW;
    const float* inb = d_int + (size_t)b * HW * 32;
    float* catb = d_cat + (size_t)b * 64 * HW;
    const float4 z4 = make_float4(0.f, 0.f, 0.f, 0.f);

    for (int half = 0; half < 2; half++) {
        int base = blockIdx.x * 512 + half * 256;
        if (base >= cnt) break;

        int e0 = base + w * 32 + p;
        int e1 = e0 + 16;
        int ent0 = (e0 < cnt) ? (int)lst[e0] : 0;
        int ent1 = (e1 < cnt) ? (int)lst[e1] : 0;
        int f0 = (e0 < cnt) ? (ent0 >> 14) : 0;
        int f1 = (e1 < cnt) ? (ent1 >> 14) : 0;
        int pix0 = ent0 & 0x3FFF, pix1 = ent1 & 0x3FFF;
        int y0 = pix0 >> 7, x0 = pix0 & 127;
        int y1 = pix1 >> 7, x1 = pix1 & 127;

        unsigned vm0 = 0, vm1 = 0;
        #pragma unroll
        for (int tap = 0; tap < 9; tap++) {
            int ky = tap / 3, kx = tap % 3;
            int ya = y0 + ky - 1, xa = x0 + kx - 1;
            int yb = y1 + ky - 1, xb = x1 + kx - 1;
            if ((unsigned)ya < 128u && (unsigned)xa < 128u) vm0 |= 1u << tap;
            if ((unsigned)yb < 128u && (unsigned)xb < 128u) vm1 |= 1u << tap;
        }
        const float* p0 = inb + ((long)(y0 - 1) * Ww + (x0 - 1)) * 32;
        const float* p1 = inb + ((long)(y1 - 1) * Ww + (x1 - 1)) * 32;

        ull acc0[8], acc1[8];
        #pragma unroll
        for (int u = 0; u < 8; u++) { acc0[u] = 0; acc1[u] = 0; }

        for (int cq = 0; cq < 8; cq++) {
            const float* kq = ks + cq * 4 * 288 + gg * 16;
            #pragma unroll
            for (int tap = 0; tap < 9; tap++) {
                const int ky = tap / 3, kx = tap % 3;
                const int off = (ky * Ww + kx) * 32 + cq * 4;
                float4 v0 = (vm0 >> tap & 1) ? __ldg((const float4*)(p0 + off)) : z4;
                float4 v1 = (vm1 >> tap & 1) ? __ldg((const float4*)(p1 + off)) : z4;
                #pragma unroll
                for (int ci = 0; ci < 4; ci++) {
                    const ulonglong2* wp = (const ulonglong2*)(kq + ci * 288 + tap * 32);
                    ulonglong2 wA = wp[0], wB = wp[1], wC = wp[2], wD = wp[3];
                    float vc0 = (ci == 0) ? v0.x : (ci == 1) ? v0.y : (ci == 2) ? v0.z : v0.w;
                    float vc1 = (ci == 0) ? v1.x : (ci == 1) ? v1.y : (ci == 2) ? v1.z : v1.w;
                    ull a0 = pack2(vc0), a1 = pack2(vc1);
                    acc0[0] = ffma2(a0, wA.x, acc0[0]); acc0[1] = ffma2(a0, wA.y, acc0[1]);
                    acc0[2] = ffma2(a0, wB.x, acc0[2]); acc0[3] = ffma2(a0, wB.y, acc0[3]);
                    acc0[4] = ffma2(a0, wC.x, acc0[4]); acc0[5] = ffma2(a0, wC.y, acc0[5]);
                    acc0[6] = ffma2(a0, wD.x, acc0[6]); acc0[7] = ffma2(a0, wD.y, acc0[7]);
                    acc1[0] = ffma2(a1, wA.x, acc1[0]); acc1[1] = ffma2(a1, wA.y, acc1[1]);
                    acc1[2] = ffma2(a1, wB.x, acc1[2]); acc1[3] = ffma2(a1, wB.y, acc1[3]);
                    acc1[4] = ffma2(a1, wC.x, acc1[4]); acc1[5] = ffma2(a1, wC.y, acc1[5]);
                    acc1[6] = ffma2(a1, wD.x, acc1[6]); acc1[7] = ffma2(a1, wD.y, acc1[7]);
                }
            }
        }

        const float* a0f = (const float*)acc0;
        const float* a1f = (const float*)acc1;
        int ob = gg * 16;
        if (f0 & 1) {
            #pragma unroll
            for (int u = 0; u < 16; u++) catb[(ob + u) * HW + pix0] = a0f[u];
        }
        if (f0 & 2) {
            #pragma unroll
            for (int u = 0; u < 16; u++) catb[(32 + ob + u) * HW + pix0] = a0f[u];
        }
        if (f1 & 1) {
            #pragma unroll
            for (int u = 0; u < 16; u++) catb[(ob + u) * HW + pix1] = a1f[u];
        }
        if (f1 & 2) {
            #pragma unroll
            for (int u = 0; u < 16; u++) catb[(32 + ob + u) * HW + pix1] = a1f[u];
        }
    }
}

// ---------------- L5: fusion conv 3x3 (64->32) + bias + residual ----------------
__global__ void __launch_bounds__(256) fusion_kernel(
    const float* __restrict__ in, const float* __restrict__ b_f,
    float* __restrict__ out) {
    extern __shared__ __align__(16) float ws[];   // [tap][ch][oo] = 18432 floats
    {
        const float4* wsrc = (const float4*)d_wft;
        float4* wdst = (float4*)ws;
        #pragma unroll
        for (int i = 0; i < 18; i++) wdst[threadIdx.x + 256 * i] = wsrc[threadIdx.x + 256 * i];
    }
    __syncthreads();

    int w = threadIdx.x >> 5, lane = threadIdx.x & 31;
    int b = blockIdx.z;
    int y = blockIdx.y * 4 + (w >> 1);
    int xh = (w & 1) * 64;
    int xa = xh + lane, xb2 = xh + 32 + lane;

    const float* catb = d_cat + (size_t)b * 64 * HW;

    ull acc0[16], acc1[16];
    #pragma unroll
    for (int u = 0; u < 16; u++) { acc0[u] = 0; acc1[u] = 0; }

    for (int ch = 0; ch < 64; ch++) {
        const float* chp = catb + (size_t)ch * HW;
        #pragma unroll
        for (int tap = 0; tap < 9; tap++) {
            const int ky = tap / 3, kx = tap % 3;
            int yy = y + ky - 1;
            bool rok = (unsigned)yy < (unsigned)Hh;
            const float* rowp = chp + yy * Ww;
            int xx0 = xa + kx - 1, xx1 = xb2 + kx - 1;
            float v0 = (rok && (unsigned)xx0 < (unsigned)Ww) ? __ldg(rowp + xx0) : 0.f;
            float v1 = (rok && (unsigned)xx1 < (unsigned)Ww) ? __ldg(rowp + xx1) : 0.f;
            ull a0 = pack2(v0), a1 = pack2(v1);
            const ulonglong2* wp = (const ulonglong2*)(ws + (tap * 64 + ch) * 32);
            #pragma unroll
            for (int q = 0; q < 8; q++) {
                ulonglong2 wq = wp[q];
                acc0[q * 2]     = ffma2(a0, wq.x, acc0[q * 2]);
                acc0[q * 2 + 1] = ffma2(a0, wq.y, acc0[q * 2 + 1]);
                acc1[q * 2]     = ffma2(a1, wq.x, acc1[q * 2]);
                acc1[q * 2 + 1] = ffma2(a1, wq.y, acc1[q * 2 + 1]);
            }
        }
    }

    const float* a0f = (const float*)acc0;
    const float* a1f = (const float*)acc1;
    long pix0 = (long)y * Ww + xa;
    long pix1 = (long)y * Ww + xb2;
    #pragma unroll
    for (int o = 0; o < 32; o++) {
        float bias = __ldg(b_f + o);
        size_t idx0 = ((size_t)(b * OUTC + o)) * HW + pix0;
        size_t idx1 = ((size_t)(b * OUTC + o)) * HW + pix1;
        out[idx0] = a0f[o] + bias + __ldg(in + idx0);
        out[idx1] = a1f[o] + bias + __ldg(in + idx1);
    }
}

// ---------------- launch ----------------
extern "C" void kernel_launch(void* const* d_in, const int* in_sizes, int n_in,
                              void* d_out, int out_size) {
    const float* input  = (const float*)d_in[0];
    const float* guide  = (const float*)d_in[1];
    const float* w1     = (const float*)d_in[2];
    const float* b1     = (const float*)d_in[3];
    const float* w2     = (const float*)d_in[4];
    const float* b2     = (const float*)d_in[5];
    const float* w_spa  = (const float*)d_in[6];
    const float* b_spa  = (const float*)d_in[7];
    const float* w_spec = (const float*)d_in[8];
    const float* b_spec = (const float*)d_in[9];
    const float* w_f    = (const float*)d_in[10];
    const float* b_f    = (const float*)d_in[11];
    float* out = (float*)d_out;

    cudaFuncSetAttribute(fusion_kernel, cudaFuncAttributeMaxDynamicSharedMemorySize, 73728);

    poolgate_kernel<<<Bb * Cc, 128>>>(input, w1, b1);
    mega_kernel<<<MEGA_KERN + MEGA_TRANS + MEGA_S1 + MEGA_WFT, 256>>>(
        input, guide, w2, b2, w_spa, b_spa, w_spec, b_spec, w_f);
    s3_emit_kernel<<<dim3(64, Bb), 256>>>();
    dynconv_kernel<<<dim3(64, Rr, Bb), 256>>>();
    fusion_kernel<<<dim3(1, 32, Bb), 256, 73728>>>(input, b_f, out);
}

// round 8
// speedup vs baseline: 2.0415x; 2.0415x over previous
#include <cuda_runtime.h>
#include <math.h>
#include <stdint.h>

#define Bb 16
#define Cc 32
#define Hh 128
#define Ww 128
#define HW 16384
#define Rr 8
#define OUTC 32

typedef unsigned long long ull;

// ---------------- scratch (device globals; no allocation) ----------------
__device__ __align__(16) float d_kern[Bb * Rr * 288 * 32];   // [b][r][c*9+kl][oo]
__device__ float          d_pool[Bb * Cc * 9];               // [b][c][kl]
__device__ float          d_gate[Bb * 576];                  // [b][rr*9+kl]
__device__ unsigned char  d_sel[Bb * HW];                    // r1 | r2<<3
__device__ int            d_segcnt[Bb * Rr * 64];
__device__ int            d_segbase[Bb * Rr * 64];
__device__ int            d_cnt[Bb * Rr];
__device__ unsigned short d_list[Bb * Rr * HW];              // pix | flags<<14 (sorted by pix)
__device__ __align__(16) float d_cat[(size_t)Bb * 64 * HW];  // CHANNEL-FIRST [b][ch][pix]
__device__ __align__(16) float d_wft[9 * 64 * 32];           // [kl][ch][o]

// ---------------- f32x2 helpers ----------------
__device__ __forceinline__ ull pack2(float v) {
    ull r; asm("mov.b64 %0, {%1, %1};" : "=l"(r) : "f"(v)); return r;
}
__device__ __forceinline__ ull ffma2(ull a, ull b, ull c) {
    ull d; asm("fma.rn.f32x2 %0, %1, %2, %3;" : "=l"(d) : "l"(a), "l"(b), "l"(c)); return d;
}

// ---------------- pool: adaptive 3x3 avg, coalesced column-striped ----------------
__global__ void __launch_bounds__(128) pool_kernel(const float* __restrict__ in) {
    int bc = blockIdx.x;
    int x = threadIdx.x;
    const float* img = in + (size_t)bc * HW;
    float rb0 = 0.f, rb1 = 0.f, rb2 = 0.f;
    #pragma unroll 4
    for (int yy = 0; yy < Hh; yy++) {
        float v = __ldg(img + yy * Ww + x);
        if (yy < 43) rb0 += v;
        if (yy >= 42 && yy < 86) rb1 += v;
        if (yy >= 85) rb2 += v;
    }
    __shared__ float srow[3][128];
    srow[0][x] = rb0; srow[1][x] = rb1; srow[2][x] = rb2;
    __syncthreads();
    if (x < 9) {
        int i = x / 3, j = x % 3;
        const int s[3] = {0, 42, 85}, e[3] = {43, 86, 128};
        const int span[3] = {43, 44, 43};
        float ssum = 0.f;
        for (int xx = s[j]; xx < e[j]; xx++) ssum += srow[i][xx];
        d_pool[bc * 9 + x] = ssum / (float)(span[i] * span[j]);
    }
}

// ---------------- gate ----------------
__global__ void __launch_bounds__(576) gate_kernel(
    const float* __restrict__ w1, const float* __restrict__ b1) {
    int b = blockIdx.x, t = threadIdx.x;
    int rr = t / 9, kl = t % 9;
    float s = __ldg(b1 + rr);
    #pragma unroll
    for (int c = 0; c < Cc; c++)
        s += d_pool[(b * Cc + c) * 9 + kl] * __ldg(w1 + rr * Cc + c);
    d_gate[b * 576 + t] = 1.f / (1.f + expf(-s));
}

// ---------------- kern gen ----------------
__global__ void __launch_bounds__(256) kern_kernel(
    const float* __restrict__ w2, const float* __restrict__ b2) {
    int idx = blockIdx.x * 256 + threadIdx.x;
    int oo = idx & 31;
    int ckl = (idx >> 5) % 288;
    int t2 = idx / (288 * 32);
    int r = t2 & 7;
    int b = t2 >> 3;
    int c = ckl / 9, kl = ckl % 9;
    int jj = r * 1024 + oo * 32 + c;
    float v = __ldg(b2 + jj);
    float4 wa = __ldg((const float4*)(w2 + jj * 8));
    float4 wb = __ldg((const float4*)(w2 + jj * 8 + 4));
    const float* gb = d_gate + b * 576 + r * 72 + kl;
    v += gb[0]  * wa.x + gb[9]  * wa.y + gb[18] * wa.z + gb[27] * wa.w;
    v += gb[36] * wb.x + gb[45] * wb.y + gb[54] * wb.z + gb[63] * wb.w;
    d_kern[idx] = v;
}

// ---------------- wf transpose: wft[kl][ch][o] ----------------
__global__ void __launch_bounds__(256) wft_kernel(const float* __restrict__ w_f) {
    int idx = blockIdx.x * 256 + threadIdx.x;
    int o = idx & 31, ch = (idx >> 5) & 63, kl = idx >> 11;
    d_wft[idx] = w_f[(o * 64 + ch) * 9 + kl];
}

// ---------------- S1: argmax select + per-segment counts ----------------
__global__ void __launch_bounds__(256) s1_select_kernel(
    const float* __restrict__ guide,
    const float* __restrict__ w_spa, const float* __restrict__ b_spa,
    const float* __restrict__ w_spec, const float* __restrict__ b_spec) {
    int t = threadIdx.x, seg = blockIdx.x, b = blockIdx.y;
    int pix = seg * 256 + t;

    float gv[Cc];
    #pragma unroll
    for (int c = 0; c < Cc; c++)
        gv[c] = __ldg(guide + ((size_t)(b * Cc + c)) * HW + pix);

    float best1 = -1e30f, best2 = -1e30f;
    int r1 = 0, r2 = 0;
    for (int r = 0; r < Rr; r++) {
        float s1 = __ldg(b_spa + r), s2 = __ldg(b_spec + r);
        #pragma unroll
        for (int c = 0; c < Cc; c++) {
            s1 += gv[c] * __ldg(w_spa + r * Cc + c);
            s2 += gv[c] * __ldg(w_spec + r * Cc + c);
        }
        if (s1 > best1) { best1 = s1; r1 = r; }
        if (s2 > best2) { best2 = s2; r2 = r; }
    }
    d_sel[b * HW + pix] = (unsigned char)(r1 | (r2 << 3));

    __shared__ int scnt[Rr];
    if (t < Rr) scnt[t] = 0;
    __syncthreads();
    if (r1 == r2) atomicAdd(&scnt[r1], 1);
    else { atomicAdd(&scnt[r1], 1); atomicAdd(&scnt[r2], 1); }
    __syncthreads();
    if (t < Rr) d_segcnt[(b * Rr + t) * 64 + seg] = scnt[t];
}

// ---------------- S2: per-list exclusive scan over segments ----------------
__global__ void s2_scan_kernel() {
    int t = threadIdx.x;
    if (t >= Bb * Rr) return;
    int s = 0;
    for (int seg = 0; seg < 64; seg++) {
        d_segbase[t * 64 + seg] = s;
        s += d_segcnt[t * 64 + seg];
    }
    d_cnt[t] = s;
}

// ---------------- S3: emit sorted lists ----------------
__global__ void __launch_bounds__(256) s3_emit_kernel() {
    int t = threadIdx.x, seg = blockIdx.x, b = blockIdx.y;
    int w = t >> 5, lane = t & 31;
    int pix = seg * 256 + t;
    int sel = d_sel[b * HW + pix];
    int r1 = sel & 7, r2 = sel >> 3;

    __shared__ int wcnt[8][8];
    int rank1 = 0, rank2 = 0;
    unsigned ltm = (1u << lane) - 1u;
    #pragma unroll
    for (int r = 0; r < Rr; r++) {
        unsigned m = __ballot_sync(0xFFFFFFFFu, (r1 == r) || (r2 == r));
        if (lane == 0) wcnt[w][r] = __popc(m);
        if (r1 == r) rank1 = __popc(m & ltm);
        if (r2 == r) rank2 = __popc(m & ltm);
    }
    __syncthreads();
    int wb1 = 0, wb2 = 0;
    for (int w2 = 0; w2 < w; w2++) { wb1 += wcnt[w2][r1]; wb2 += wcnt[w2][r2]; }

    unsigned short pv = (unsigned short)pix;
    if (r1 == r2) {
        int off = d_segbase[(b * Rr + r1) * 64 + seg] + wb1 + rank1;
        d_list[(b * Rr + r1) * HW + off] = (unsigned short)(pv | (3u << 14));
    } else {
        int off1 = d_segbase[(b * Rr + r1) * 64 + seg] + wb1 + rank1;
        d_list[(b * Rr + r1) * HW + off1] = (unsigned short)(pv | (1u << 14));
        int off2 = d_segbase[(b * Rr + r2) * 64 + seg] + wb2 + rank2;
        d_list[(b * Rr + r2) * HW + off2] = (unsigned short)(pv | (2u << 14));
    }
}

// ---------------- dynconv v4: lane=pixel, all 32 oo per lane, NCHW scalar gathers ----------------
// grid (32, 8, 16), block 256 (8 warps). Warp: 2 streams x 32 lanes = 64 entries; block = 512.
__global__ void __launch_bounds__(256) dynconv_kernel(const float* __restrict__ in) {
    int b = blockIdx.z, r = blockIdx.y;
    int cnt = d_cnt[b * Rr + r];
    int base = blockIdx.x * 512;
    if (base >= cnt) return;

    __shared__ __align__(16) float ks[288 * 32];   // [c*9+tap][oo]
    {
        const float4* kg = (const float4*)(d_kern + (size_t)(b * Rr + r) * 9216);
        float4* kd = (float4*)ks;
        #pragma unroll
        for (int i = 0; i < 9; i++) kd[threadIdx.x + 256 * i] = kg[threadIdx.x + 256 * i];
    }
    __syncthreads();

    int w = threadIdx.x >> 5, lane = threadIdx.x & 31;
    const unsigned short* lst = d_list + (b * Rr + r) * HW;
    const float* inb = in + (size_t)b * Cc * HW;

    int e0 = base + w * 64 + lane;
    int e1 = e0 + 32;
    int ent0 = (e0 < cnt) ? (int)lst[e0] : 0;
    int ent1 = (e1 < cnt) ? (int)lst[e1] : 0;
    int f0 = (e0 < cnt) ? (ent0 >> 14) : 0;
    int f1 = (e1 < cnt) ? (ent1 >> 14) : 0;
    int pix0 = ent0 & 0x3FFF, pix1 = ent1 & 0x3FFF;
    int y0 = pix0 >> 7, x0 = pix0 & 127;
    int y1 = pix1 >> 7, x1 = pix1 & 127;

    unsigned vm0 = 0, vm1 = 0;
    #pragma unroll
    for (int tap = 0; tap < 9; tap++) {
        int ky = tap / 3, kx = tap % 3;
        if ((unsigned)(y0 + ky - 1) < 128u && (unsigned)(x0 + kx - 1) < 128u) vm0 |= 1u << tap;
        if ((unsigned)(y1 + ky - 1) < 128u && (unsigned)(x1 + kx - 1) < 128u) vm1 |= 1u << tap;
    }
    if (f0 == 0) vm0 = 0;
    if (f1 == 0) vm1 = 0;

    const int DOFF[9] = {-Ww - 1, -Ww, -Ww + 1, -1, 0, 1, Ww - 1, Ww, Ww + 1};

    ull acc0[16], acc1[16];
    #pragma unroll
    for (int u = 0; u < 16; u++) { acc0[u] = 0; acc1[u] = 0; }

    for (int c = 0; c < Cc; c++) {
        const float* inc = inb + (size_t)c * HW;
        const float* kc = ks + c * 288;
        #pragma unroll
        for (int tap = 0; tap < 9; tap++) {
            float v0 = (vm0 >> tap & 1) ? __ldg(inc + pix0 + DOFF[tap]) : 0.f;
            float v1 = (vm1 >> tap & 1) ? __ldg(inc + pix1 + DOFF[tap]) : 0.f;
            ull a0 = pack2(v0), a1 = pack2(v1);
            const ulonglong2* wp = (const ulonglong2*)(kc + tap * 32);
            #pragma unroll
            for (int q = 0; q < 8; q++) {
                ulonglong2 wq = wp[q];
                acc0[q * 2]     = ffma2(a0, wq.x, acc0[q * 2]);
                acc0[q * 2 + 1] = ffma2(a0, wq.y, acc0[q * 2 + 1]);
                acc1[q * 2]     = ffma2(a1, wq.x, acc1[q * 2]);
                acc1[q * 2 + 1] = ffma2(a1, wq.y, acc1[q * 2 + 1]);
            }
        }
    }

    float* catb = d_cat + (size_t)b * 64 * HW;
    const float* a0f = (const float*)acc0;
    const float* a1f = (const float*)acc1;
    if (f0 & 1) {
        #pragma unroll
        for (int u = 0; u < 32; u++) catb[u * HW + pix0] = a0f[u];
    }
    if (f0 & 2) {
        #pragma unroll
        for (int u = 0; u < 32; u++) catb[(32 + u) * HW + pix0] = a0f[u];
    }
    if (f1 & 1) {
        #pragma unroll
        for (int u = 0; u < 32; u++) catb[u * HW + pix1] = a1f[u];
    }
    if (f1 & 2) {
        #pragma unroll
        for (int u = 0; u < 32; u++) catb[(32 + u) * HW + pix1] = a1f[u];
    }
}

// ---------------- fusion conv 3x3 (64->32) + bias + residual (unchanged from R5) ----------------
__global__ void __launch_bounds__(256) fusion_kernel(
    const float* __restrict__ in, const float* __restrict__ b_f,
    float* __restrict__ out) {
    extern __shared__ __align__(16) float ws[];   // [tap][ch][oo] = 18432 floats
    {
        const float4* wsrc = (const float4*)d_wft;
        float4* wdst = (float4*)ws;
        #pragma unroll
        for (int i = 0; i < 18; i++) wdst[threadIdx.x + 256 * i] = wsrc[threadIdx.x + 256 * i];
    }
    __syncthreads();

    int w = threadIdx.x >> 5, lane = threadIdx.x & 31;
    int b = blockIdx.z;
    int y = blockIdx.y * 4 + (w >> 1);
    int xh = (w & 1) * 64;
    int xa = xh + lane, xb2 = xh + 32 + lane;

    const float* catb = d_cat + (size_t)b * 64 * HW;

    ull acc0[16], acc1[16];
    #pragma unroll
    for (int u = 0; u < 16; u++) { acc0[u] = 0; acc1[u] = 0; }

    for (int ch = 0; ch < 64; ch++) {
        const float* chp = catb + (size_t)ch * HW;
        #pragma unroll
        for (int tap = 0; tap < 9; tap++) {
            const int ky = tap / 3, kx = tap % 3;
            int yy = y + ky - 1;
            bool rok = (unsigned)yy < (unsigned)Hh;
            const float* rowp = chp + yy * Ww;
            int xx0 = xa + kx - 1, xx1 = xb2 + kx - 1;
            float v0 = (rok && (unsigned)xx0 < (unsigned)Ww) ? __ldg(rowp + xx0) : 0.f;
            float v1 = (rok && (unsigned)xx1 < (unsigned)Ww) ? __ldg(rowp + xx1) : 0.f;
            ull a0 = pack2(v0), a1 = pack2(v1);
            const ulonglong2* wp = (const ulonglong2*)(ws + (tap * 64 + ch) * 32);
            #pragma unroll
            for (int q = 0; q < 8; q++) {
                ulonglong2 wq = wp[q];
                acc0[q * 2]     = ffma2(a0, wq.x, acc0[q * 2]);
                acc0[q * 2 + 1] = ffma2(a0, wq.y, acc0[q * 2 + 1]);
                acc1[q * 2]     = ffma2(a1, wq.x, acc1[q * 2]);
                acc1[q * 2 + 1] = ffma2(a1, wq.y, acc1[q * 2 + 1]);
            }
        }
    }

    const float* a0f = (const float*)acc0;
    const float* a1f = (const float*)acc1;
    long pix0 = (long)y * Ww + xa;
    long pix1 = (long)y * Ww + xb2;
    #pragma unroll
    for (int o = 0; o < 32; o++) {
        float bias = __ldg(b_f + o);
        size_t idx0 = ((size_t)(b * OUTC + o)) * HW + pix0;
        size_t idx1 = ((size_t)(b * OUTC + o)) * HW + pix1;
        out[idx0] = a0f[o] + bias + __ldg(in + idx0);
        out[idx1] = a1f[o] + bias + __ldg(in + idx1);
    }
}

// ---------------- launch ----------------
extern "C" void kernel_launch(void* const* d_in, const int* in_sizes, int n_in,
                              void* d_out, int out_size) {
    const float* input  = (const float*)d_in[0];
    const float* guide  = (const float*)d_in[1];
    const float* w1     = (const float*)d_in[2];
    const float* b1     = (const float*)d_in[3];
    const float* w2     = (const float*)d_in[4];
    const float* b2     = (const float*)d_in[5];
    const float* w_spa  = (const float*)d_in[6];
    const float* b_spa  = (const float*)d_in[7];
    const float* w_spec = (const float*)d_in[8];
    const float* b_spec = (const float*)d_in[9];
    const float* w_f    = (const float*)d_in[10];
    const float* b_f    = (const float*)d_in[11];
    float* out = (float*)d_out;

    cudaFuncSetAttribute(fusion_kernel, cudaFuncAttributeMaxDynamicSharedMemorySize, 73728);

    pool_kernel<<<Bb * Cc, 128>>>(input);
    gate_kernel<<<Bb, 576>>>(w1, b1);
    kern_kernel<<<Bb * Rr * 288 * 32 / 256, 256>>>(w2, b2);
    wft_kernel<<<72, 256>>>(w_f);
    s1_select_kernel<<<dim3(64, Bb), 256>>>(guide, w_spa, b_spa, w_spec, b_spec);
    s2_scan_kernel<<<1, 128>>>();
    s3_emit_kernel<<<dim3(64, Bb), 256>>>();
    dynconv_kernel<<<dim3(32, Rr, Bb), 256>>>(input);
    fusion_kernel<<<dim3(1, 32, Bb), 256, 73728>>>(input, b_f, out);
}

// round 10
// speedup vs baseline: 2.2264x; 1.0906x over previous
#include <cuda_runtime.h>
#include <math.h>
#include <stdint.h>

#define Bb 16
#define Cc 32
#define Hh 128
#define Ww 128
#define HW 16384
#define Rr 8
#define OUTC 32

typedef unsigned long long ull;

// ---------------- scratch (device globals; no allocation) ----------------
__device__ __align__(16) float d_kern[Bb * Rr * 288 * 32];   // [b][r][c*9+kl][oo]
__device__ float          d_pool[Bb * Cc * 9];               // [b][c][kl]
__device__ float          d_gate[Bb * 576];                  // [b][rr*9+kl]
__device__ unsigned char  d_sel[Bb * HW];                    // r1 | r2<<3
__device__ int            d_segcnt[Bb * Rr * 64];
__device__ int            d_segbase[Bb * Rr * 64];
__device__ int            d_cnt[Bb * Rr];
__device__ unsigned short d_list[Bb * Rr * HW];              // pix | flags<<14 (sorted by pix)
__device__ __align__(16) float d_cat[(size_t)Bb * 64 * HW];  // CHANNEL-FIRST [b][ch][pix]
__device__ __align__(16) float d_wft[9 * 64 * 32];           // [kl][ch][o]

// ---------------- f32x2 helpers ----------------
__device__ __forceinline__ ull pack2(float v) {
    ull r; asm("mov.b64 %0, {%1, %1};" : "=l"(r) : "f"(v)); return r;
}
__device__ __forceinline__ ull ffma2(ull a, ull b, ull c) {
    ull d; asm("fma.rn.f32x2 %0, %1, %2, %3;" : "=l"(d) : "l"(a), "l"(b), "l"(c)); return d;
}

// ================= L1: pool (2 images/block) | s1 select | wft =================
#define L1_POOL 256
#define L1_S1   1024
#define L1_WFT  72

__global__ void __launch_bounds__(256) l1_kernel(
    const float* __restrict__ in, const float* __restrict__ guide,
    const float* __restrict__ w_spa, const float* __restrict__ b_spa,
    const float* __restrict__ w_spec, const float* __restrict__ b_spec,
    const float* __restrict__ w_f) {
    int blk = blockIdx.x, t = threadIdx.x;
    __shared__ float srow[2][3][128];
    __shared__ int scnt[Rr];

    if (blk < L1_POOL) {
        // ---- adaptive 3x3 avg pool, 2 images per block, coalesced columns ----
        int half = t >> 7, x = t & 127;
        int bc = blk * 2 + half;
        const float* img = in + (size_t)bc * HW;
        float rb0 = 0.f, rb1 = 0.f, rb2 = 0.f;
        #pragma unroll 4
        for (int yy = 0; yy < Hh; yy++) {
            float v = __ldg(img + yy * Ww + x);
            if (yy < 43) rb0 += v;
            if (yy >= 42 && yy < 86) rb1 += v;
            if (yy >= 85) rb2 += v;
        }
        srow[half][0][x] = rb0; srow[half][1][x] = rb1; srow[half][2][x] = rb2;
        __syncthreads();
        if (t < 18) {
            int h2 = t / 9, k = t % 9;
            int i = k / 3, j = k % 3;
            const int s[3] = {0, 42, 85}, e[3] = {43, 86, 128};
            const int span[3] = {43, 44, 43};
            float ssum = 0.f;
            for (int xx = s[j]; xx < e[j]; xx++) ssum += srow[h2][i][xx];
            d_pool[(blk * 2 + h2) * 9 + k] = ssum / (float)(span[i] * span[j]);
        }
    } else if (blk < L1_POOL + L1_S1) {
        // ---- s1: argmax select + per-segment counts ----
        int sb = blk - L1_POOL;
        int seg = sb & 63, b = sb >> 6;
        int pix = seg * 256 + t;

        float gv[Cc];
        #pragma unroll
        for (int c = 0; c < Cc; c++)
            gv[c] = __ldg(guide + ((size_t)(b * Cc + c)) * HW + pix);

        float best1 = -1e30f, best2 = -1e30f;
        int r1 = 0, r2 = 0;
        for (int r = 0; r < Rr; r++) {
            float s1 = __ldg(b_spa + r), s2 = __ldg(b_spec + r);
            #pragma unroll
            for (int c = 0; c < Cc; c++) {
                s1 += gv[c] * __ldg(w_spa + r * Cc + c);
                s2 += gv[c] * __ldg(w_spec + r * Cc + c);
            }
            if (s1 > best1) { best1 = s1; r1 = r; }
            if (s2 > best2) { best2 = s2; r2 = r; }
        }
        d_sel[b * HW + pix] = (unsigned char)(r1 | (r2 << 3));

        if (t < Rr) scnt[t] = 0;
        __syncthreads();
        if (r1 == r2) atomicAdd(&scnt[r1], 1);
        else { atomicAdd(&scnt[r1], 1); atomicAdd(&scnt[r2], 1); }
        __syncthreads();
        if (t < Rr) d_segcnt[(b * Rr + t) * 64 + seg] = scnt[t];
    } else {
        // ---- fusion weight transpose: wft[kl][ch][o] ----
        int idx = (blk - L1_POOL - L1_S1) * 256 + t;
        int o = idx & 31, ch = (idx >> 5) & 63, kl = idx >> 11;
        d_wft[idx] = w_f[(o * 64 + ch) * 9 + kl];
    }
}

// ================= L2: gate (16 blocks) | s2 scan (1 block) =================
__global__ void __launch_bounds__(256) l2_kernel(
    const float* __restrict__ w1, const float* __restrict__ b1) {
    int blk = blockIdx.x, t = threadIdx.x;
    if (blk < Bb) {
        int b = blk;
        for (int i = t; i < 576; i += 256) {
            int rr = i / 9, kl = i % 9;
            float s = __ldg(b1 + rr);
            #pragma unroll
            for (int c = 0; c < Cc; c++)
                s += d_pool[(b * Cc + c) * 9 + kl] * __ldg(w1 + rr * Cc + c);
            d_gate[b * 576 + i] = 1.f / (1.f + expf(-s));
        }
    } else {
        if (t < Bb * Rr) {
            int s = 0;
            for (int seg = 0; seg < 64; seg++) {
                d_segbase[t * 64 + seg] = s;
                s += d_segcnt[t * 64 + seg];
            }
            d_cnt[t] = s;
        }
    }
}

// ================= L3: kern gen (4608 blocks) | s3 emit (1024 blocks) =================
#define L3_KERN 4608

__global__ void __launch_bounds__(256) l3_kernel(
    const float* __restrict__ w2, const float* __restrict__ b2) {
    int blk = blockIdx.x, t = threadIdx.x;
    __shared__ int wcnt[8][8];

    if (blk < L3_KERN) {
        int idx = blk * 256 + t;
        int oo = idx & 31;
        int ckl = (idx >> 5) % 288;
        int t2 = idx / (288 * 32);
        int r = t2 & 7;
        int b = t2 >> 3;
        int c = ckl / 9, kl = ckl % 9;
        int jj = r * 1024 + oo * 32 + c;
        float v = __ldg(b2 + jj);
        float4 wa = __ldg((const float4*)(w2 + jj * 8));
        float4 wb = __ldg((const float4*)(w2 + jj * 8 + 4));
        const float* gb = d_gate + b * 576 + r * 72 + kl;
        v += gb[0]  * wa.x + gb[9]  * wa.y + gb[18] * wa.z + gb[27] * wa.w;
        v += gb[36] * wb.x + gb[45] * wb.y + gb[54] * wb.z + gb[63] * wb.w;
        d_kern[idx] = v;
    } else {
        int sb = blk - L3_KERN;
        int seg = sb & 63, b = sb >> 6;
        int w = t >> 5, lane = t & 31;
        int pix = seg * 256 + t;
        int sel = d_sel[b * HW + pix];
        int r1 = sel & 7, r2 = sel >> 3;

        int rank1 = 0, rank2 = 0;
        unsigned ltm = (1u << lane) - 1u;
        #pragma unroll
        for (int r = 0; r < Rr; r++) {
            unsigned m = __ballot_sync(0xFFFFFFFFu, (r1 == r) || (r2 == r));
            if (lane == 0) wcnt[w][r] = __popc(m);
            if (r1 == r) rank1 = __popc(m & ltm);
            if (r2 == r) rank2 = __popc(m & ltm);
        }
        __syncthreads();
        int wb1 = 0, wb2 = 0;
        for (int w2i = 0; w2i < w; w2i++) { wb1 += wcnt[w2i][r1]; wb2 += wcnt[w2i][r2]; }

        unsigned short pv = (unsigned short)pix;
        if (r1 == r2) {
            int off = d_segbase[(b * Rr + r1) * 64 + seg] + wb1 + rank1;
            d_list[(b * Rr + r1) * HW + off] = (unsigned short)(pv | (3u << 14));
        } else {
            int off1 = d_segbase[(b * Rr + r1) * 64 + seg] + wb1 + rank1;
            d_list[(b * Rr + r1) * HW + off1] = (unsigned short)(pv | (1u << 14));
            int off2 = d_segbase[(b * Rr + r2) * 64 + seg] + wb2 + rank2;
            d_list[(b * Rr + r2) * HW + off2] = (unsigned short)(pv | (2u << 14));
        }
    }
}

// ================= L4: dynconv (unchanged from R8) =================
__global__ void __launch_bounds__(256) dynconv_kernel(const float* __restrict__ in) {
    int b = blockIdx.z, r = blockIdx.y;
    int cnt = d_cnt[b * Rr + r];
    int base = blockIdx.x * 512;
    if (base >= cnt) return;

    __shared__ __align__(16) float ks[288 * 32];   // [c*9+tap][oo]
    {
        const float4* kg = (const float4*)(d_kern + (size_t)(b * Rr + r) * 9216);
        float4* kd = (float4*)ks;
        #pragma unroll
        for (int i = 0; i < 9; i++) kd[threadIdx.x + 256 * i] = kg[threadIdx.x + 256 * i];
    }
    __syncthreads();

    int w = threadIdx.x >> 5, lane = threadIdx.x & 31;
    const unsigned short* lst = d_list + (b * Rr + r) * HW;
    const float* inb = in + (size_t)b * Cc * HW;

    int e0 = base + w * 64 + lane;
    int e1 = e0 + 32;
    int ent0 = (e0 < cnt) ? (int)lst[e0] : 0;
    int ent1 = (e1 < cnt) ? (int)lst[e1] : 0;
    int f0 = (e0 < cnt) ? (ent0 >> 14) : 0;
    int f1 = (e1 < cnt) ? (ent1 >> 14) : 0;
    int pix0 = ent0 & 0x3FFF, pix1 = ent1 & 0x3FFF;
    int y0 = pix0 >> 7, x0 = pix0 & 127;
    int y1 = pix1 >> 7, x1 = pix1 & 127;

    unsigned vm0 = 0, vm1 = 0;
    #pragma unroll
    for (int tap = 0; tap < 9; tap++) {
        int ky = tap / 3, kx = tap % 3;
        if ((unsigned)(y0 + ky - 1) < 128u && (unsigned)(x0 + kx - 1) < 128u) vm0 |= 1u << tap;
        if ((unsigned)(y1 + ky - 1) < 128u && (unsigned)(x1 + kx - 1) < 128u) vm1 |= 1u << tap;
    }
    if (f0 == 0) vm0 = 0;
    if (f1 == 0) vm1 = 0;

    const int DOFF[9] = {-Ww - 1, -Ww, -Ww + 1, -1, 0, 1, Ww - 1, Ww, Ww + 1};

    ull acc0[16], acc1[16];
    #pragma unroll
    for (int u = 0; u < 16; u++) { acc0[u] = 0; acc1[u] = 0; }

    for (int c = 0; c < Cc; c++) {
        const float* inc = inb + (size_t)c * HW;
        const float* kc = ks + c * 288;
        #pragma unroll
        for (int tap = 0; tap < 9; tap++) {
            float v0 = (vm0 >> tap & 1) ? __ldg(inc + pix0 + DOFF[tap]) : 0.f;
            float v1 = (vm1 >> tap & 1) ? __ldg(inc + pix1 + DOFF[tap]) : 0.f;
            ull a0 = pack2(v0), a1 = pack2(v1);
            const ulonglong2* wp = (const ulonglong2*)(kc + tap * 32);
            #pragma unroll
            for (int q = 0; q < 8; q++) {
                ulonglong2 wq = wp[q];
                acc0[q * 2]     = ffma2(a0, wq.x, acc0[q * 2]);
                acc0[q * 2 + 1] = ffma2(a0, wq.y, acc0[q * 2 + 1]);
                acc1[q * 2]     = ffma2(a1, wq.x, acc1[q * 2]);
                acc1[q * 2 + 1] = ffma2(a1, wq.y, acc1[q * 2 + 1]);
            }
        }
    }

    float* catb = d_cat + (size_t)b * 64 * HW;
    const float* a0f = (const float*)acc0;
    const float* a1f = (const float*)acc1;
    if (f0 & 1) {
        #pragma unroll
        for (int u = 0; u < 32; u++) catb[u * HW + pix0] = a0f[u];
    }
    if (f0 & 2) {
        #pragma unroll
        for (int u = 0; u < 32; u++) catb[(32 + u) * HW + pix0] = a0f[u];
    }
    if (f1 & 1) {
        #pragma unroll
        for (int u = 0; u < 32; u++) catb[u * HW + pix1] = a1f[u];
    }
    if (f1 & 2) {
        #pragma unroll
        for (int u = 0; u < 32; u++) catb[(32 + u) * HW + pix1] = a1f[u];
    }
}

// ================= L5: fusion conv, single-wave grid (256 blocks x 8 rows) =================
__global__ void __launch_bounds__(256) fusion_kernel(
    const float* __restrict__ in, const float* __restrict__ b_f,
    float* __restrict__ out) {
    extern __shared__ __align__(16) float ws[];   // [tap][ch][oo] = 18432 floats
    {
        const float4* wsrc = (const float4*)d_wft;
        float4* wdst = (float4*)ws;
        #pragma unroll
        for (int i = 0; i < 18; i++) wdst[threadIdx.x + 256 * i] = wsrc[threadIdx.x + 256 * i];
    }
    __syncthreads();

    int w = threadIdx.x >> 5, lane = threadIdx.x & 31;
    int b = blockIdx.y;
    int xh = (w & 1) * 64;
    int xa = xh + lane, xb2 = xh + 32 + lane;
    const float* catb = d_cat + (size_t)b * 64 * HW;

    for (int pass = 0; pass < 2; pass++) {
        int y = blockIdx.x * 8 + pass * 4 + (w >> 1);

        ull acc0[16], acc1[16];
        #pragma unroll
        for (int u = 0; u < 16; u++) { acc0[u] = 0; acc1[u] = 0; }

        for (int ch = 0; ch < 64; ch++) {
            const float* chp = catb + (size_t)ch * HW;
            #pragma unroll
            for (int tap = 0; tap < 9; tap++) {
                const int ky = tap / 3, kx = tap % 3;
                int yy = y + ky - 1;
                bool rok = (unsigned)yy < (unsigned)Hh;
                const float* rowp = chp + yy * Ww;
                int xx0 = xa + kx - 1, xx1 = xb2 + kx - 1;
                float v0 = (rok && (unsigned)xx0 < (unsigned)Ww) ? __ldg(rowp + xx0) : 0.f;
                float v1 = (rok && (unsigned)xx1 < (unsigned)Ww) ? __ldg(rowp + xx1) : 0.f;
                ull a0 = pack2(v0), a1 = pack2(v1);
                const ulonglong2* wp = (const ulonglong2*)(ws + (tap * 64 + ch) * 32);
                #pragma unroll
                for (int q = 0; q < 8; q++) {
                    ulonglong2 wq = wp[q];
                    acc0[q * 2]     = ffma2(a0, wq.x, acc0[q * 2]);
                    acc0[q * 2 + 1] = ffma2(a0, wq.y, acc0[q * 2 + 1]);
                    acc1[q * 2]     = ffma2(a1, wq.x, acc1[q * 2]);
                    acc1[q * 2 + 1] = ffma2(a1, wq.y, acc1[q * 2 + 1]);
                }
            }
        }

        const float* a0f = (const float*)acc0;
        const float* a1f = (const float*)acc1;
        long pix0 = (long)y * Ww + xa;
        long pix1 = (long)y * Ww + xb2;
        #pragma unroll
        for (int o = 0; o < 32; o++) {
            float bias = __ldg(b_f + o);
            size_t idx0 = ((size_t)(b * OUTC + o)) * HW + pix0;
            size_t idx1 = ((size_t)(b * OUTC + o)) * HW + pix1;
            out[idx0] = a0f[o] + bias + __ldg(in + idx0);
            out[idx1] = a1f[o] + bias + __ldg(in + idx1);
        }
    }
}

// ---------------- launch ----------------
extern "C" void kernel_launch(void* const* d_in, const int* in_sizes, int n_in,
                              void* d_out, int out_size) {
    const float* input  = (const float*)d_in[0];
    const float* guide  = (const float*)d_in[1];
    const float* w1     = (const float*)d_in[2];
    const float* b1     = (const float*)d_in[3];
    const float* w2     = (const float*)d_in[4];
    const float* b2     = (const float*)d_in[5];
    const float* w_spa  = (const float*)d_in[6];
    const float* b_spa  = (const float*)d_in[7];
    const float* w_spec = (const float*)d_in[8];
    const float* b_spec = (const float*)d_in[9];
    const float* w_f    = (const float*)d_in[10];
    const float* b_f    = (const float*)d_in[11];
    float* out = (float*)d_out;

    cudaFuncSetAttribute(fusion_kernel, cudaFuncAttributeMaxDynamicSharedMemorySize, 73728);

    l1_kernel<<<L1_POOL + L1_S1 + L1_WFT, 256>>>(input, guide, w_spa, b_spa, w_spec, b_spec, w_f);
    l2_kernel<<<Bb + 1, 256>>>(w1, b1);
    l3_kernel<<<L3_KERN + 1024, 256>>>(w2, b2);
    dynconv_kernel<<<dim3(32, Rr, Bb), 256>>>(input);
    fusion_kernel<<<dim3(16, Bb), 256, 73728>>>(input, b_f, out);
}

// round 11
// speedup vs baseline: 3.6587x; 1.6433x over previous
#include <cuda_runtime.h>
#include <cuda_bf16.h>
#include <math.h>
#include <stdint.h>

#define Bb 16
#define Cc 32
#define Hh 128
#define Ww 128
#define HW 16384
#define Rr 8
#define OUTC 32

typedef unsigned long long ull;

// ---------------- scratch (device globals; no allocation) ----------------
__device__ __align__(16) float d_kern[Bb * Rr * 288 * 32];   // [b][r][c*9+kl][oo]
__device__ float          d_pool[Bb * Cc * 9];               // [b][c][kl]
__device__ float          d_gate[Bb * 576];                  // [b][rr*9+kl]
__device__ unsigned char  d_sel[Bb * HW];                    // r1 | r2<<3
__device__ int            d_segcnt[Bb * Rr * 64];
__device__ int            d_segbase[Bb * Rr * 64];
__device__ int            d_cnt[Bb * Rr];
__device__ unsigned short d_list[Bb * Rr * HW];              // pix | flags<<14 (sorted by pix)
__device__ __align__(16) float d_cat[(size_t)Bb * HW * 64];  // PIXEL-MAJOR [b][pix][ch] (spa 0-31, spec 32-63)
__device__ __align__(16) unsigned short d_wfbh[9 * 32 * 64]; // bf16 hi [tap][oo][ch]
__device__ __align__(16) unsigned short d_wfbl[9 * 32 * 64]; // bf16 lo [tap][oo][ch]

// ---------------- f32x2 / bit helpers ----------------
__device__ __forceinline__ ull pack2(float v) {
    ull r; asm("mov.b64 %0, {%1, %1};" : "=l"(r) : "f"(v)); return r;
}
__device__ __forceinline__ ull ffma2(ull a, ull b, ull c) {
    ull d; asm("fma.rn.f32x2 %0, %1, %2, %3;" : "=l"(d) : "l"(a), "l"(b), "l"(c)); return d;
}
__device__ __forceinline__ uint32_t prmt7632(uint32_t a, uint32_t b) {
    uint32_t r; asm("prmt.b32 %0, %1, %2, 0x7632;" : "=r"(r) : "r"(a), "r"(b)); return r;
}
__device__ __forceinline__ uint32_t smem_u32(const void* p) {
    uint32_t a;
    asm("{ .reg .u64 t; cvta.to.shared.u64 t, %1; cvt.u32.u64 %0, t; }" : "=r"(a) : "l"(p));
    return a;
}
#define LDSM4(r0, r1, r2, r3, addr) \
    asm volatile("ldmatrix.sync.aligned.m8n8.x4.shared.b16 {%0,%1,%2,%3}, [%4];" \
                 : "=r"(r0), "=r"(r1), "=r"(r2), "=r"(r3) : "r"(addr))
#define MMA16816(c, a0, a1, a2, a3, b0, b1) \
    asm volatile("mma.sync.aligned.m16n8k16.row.col.f32.bf16.bf16.f32 " \
                 "{%0,%1,%2,%3},{%4,%5,%6,%7},{%8,%9},{%0,%1,%2,%3};" \
                 : "+f"((c)[0]), "+f"((c)[1]), "+f"((c)[2]), "+f"((c)[3]) \
                 : "r"(a0), "r"(a1), "r"(a2), "r"(a3), "r"(b0), "r"(b1))

// ================= L1: pool (2 images/block) | s1 select | wf bf16-split =================
#define L1_POOL 256
#define L1_S1   1024
#define L1_WFT  72

__global__ void __launch_bounds__(256) l1_kernel(
    const float* __restrict__ in, const float* __restrict__ guide,
    const float* __restrict__ w_spa, const float* __restrict__ b_spa,
    const float* __restrict__ w_spec, const float* __restrict__ b_spec,
    const float* __restrict__ w_f) {
    int blk = blockIdx.x, t = threadIdx.x;
    __shared__ float srow[2][3][128];
    __shared__ int scnt[Rr];

    if (blk < L1_POOL) {
        int half = t >> 7, x = t & 127;
        int bc = blk * 2 + half;
        const float* img = in + (size_t)bc * HW;
        float rb0 = 0.f, rb1 = 0.f, rb2 = 0.f;
        #pragma unroll 4
        for (int yy = 0; yy < Hh; yy++) {
            float v = __ldg(img + yy * Ww + x);
            if (yy < 43) rb0 += v;
            if (yy >= 42 && yy < 86) rb1 += v;
            if (yy >= 85) rb2 += v;
        }
        srow[half][0][x] = rb0; srow[half][1][x] = rb1; srow[half][2][x] = rb2;
        __syncthreads();
        if (t < 18) {
            int h2 = t / 9, k = t % 9;
            int i = k / 3, j = k % 3;
            const int s[3] = {0, 42, 85}, e[3] = {43, 86, 128};
            const int span[3] = {43, 44, 43};
            float ssum = 0.f;
            for (int xx = s[j]; xx < e[j]; xx++) ssum += srow[h2][i][xx];
            d_pool[(blk * 2 + h2) * 9 + k] = ssum / (float)(span[i] * span[j]);
        }
    } else if (blk < L1_POOL + L1_S1) {
        int sb = blk - L1_POOL;
        int seg = sb & 63, b = sb >> 6;
        int pix = seg * 256 + t;

        float gv[Cc];
        #pragma unroll
        for (int c = 0; c < Cc; c++)
            gv[c] = __ldg(guide + ((size_t)(b * Cc + c)) * HW + pix);

        float best1 = -1e30f, best2 = -1e30f;
        int r1 = 0, r2 = 0;
        for (int r = 0; r < Rr; r++) {
            float s1 = __ldg(b_spa + r), s2 = __ldg(b_spec + r);
            #pragma unroll
            for (int c = 0; c < Cc; c++) {
                s1 += gv[c] * __ldg(w_spa + r * Cc + c);
                s2 += gv[c] * __ldg(w_spec + r * Cc + c);
            }
            if (s1 > best1) { best1 = s1; r1 = r; }
            if (s2 > best2) { best2 = s2; r2 = r; }
        }
        d_sel[b * HW + pix] = (unsigned char)(r1 | (r2 << 3));

        if (t < Rr) scnt[t] = 0;
        __syncthreads();
        if (r1 == r2) atomicAdd(&scnt[r1], 1);
        else { atomicAdd(&scnt[r1], 1); atomicAdd(&scnt[r2], 1); }
        __syncthreads();
        if (t < Rr) d_segcnt[(b * Rr + t) * 64 + seg] = scnt[t];
    } else {
        // fusion weights -> bf16 truncation split, layout [tap][oo][ch]
        int idx = (blk - L1_POOL - L1_S1) * 256 + t;
        int ch = idx & 63, o = (idx >> 6) & 31, tap = idx >> 11;
        float v = w_f[(o * 64 + ch) * 9 + tap];
        uint32_t uv = __float_as_uint(v);
        uint32_t hv = uv & 0xFFFF0000u;
        float lo = v - __uint_as_float(hv);
        d_wfbh[idx] = (unsigned short)(hv >> 16);
        __nv_bfloat16 lb = __float2bfloat16(lo);
        d_wfbl[idx] = *reinterpret_cast<unsigned short*>(&lb);
    }
}

// ================= L2: gate (16 blocks) | s2 scan (1 block) =================
__global__ void __launch_bounds__(256) l2_kernel(
    const float* __restrict__ w1, const float* __restrict__ b1) {
    int blk = blockIdx.x, t = threadIdx.x;
    if (blk < Bb) {
        int b = blk;
        for (int i = t; i < 576; i += 256) {
            int rr = i / 9, kl = i % 9;
            float s = __ldg(b1 + rr);
            #pragma unroll
            for (int c = 0; c < Cc; c++)
                s += d_pool[(b * Cc + c) * 9 + kl] * __ldg(w1 + rr * Cc + c);
            d_gate[b * 576 + i] = 1.f / (1.f + expf(-s));
        }
    } else {
        if (t < Bb * Rr) {
            int s = 0;
            for (int seg = 0; seg < 64; seg++) {
                d_segbase[t * 64 + seg] = s;
                s += d_segcnt[t * 64 + seg];
            }
            d_cnt[t] = s;
        }
    }
}

// ================= L3: kern gen (4608 blocks) | s3 emit (1024 blocks) =================
#define L3_KERN 4608

__global__ void __launch_bounds__(256) l3_kernel(
    const float* __restrict__ w2, const float* __restrict__ b2) {
    int blk = blockIdx.x, t = threadIdx.x;
    __shared__ int wcnt[8][8];

    if (blk < L3_KERN) {
        int idx = blk * 256 + t;
        int oo = idx & 31;
        int ckl = (idx >> 5) % 288;
        int t2 = idx / (288 * 32);
        int r = t2 & 7;
        int b = t2 >> 3;
        int c = ckl / 9, kl = ckl % 9;
        int jj = r * 1024 + oo * 32 + c;
        float v = __ldg(b2 + jj);
        float4 wa = __ldg((const float4*)(w2 + jj * 8));
        float4 wb = __ldg((const float4*)(w2 + jj * 8 + 4));
        const float* gb = d_gate + b * 576 + r * 72 + kl;
        v += gb[0]  * wa.x + gb[9]  * wa.y + gb[18] * wa.z + gb[27] * wa.w;
        v += gb[36] * wb.x + gb[45] * wb.y + gb[54] * wb.z + gb[63] * wb.w;
        d_kern[idx] = v;
    } else {
        int sb = blk - L3_KERN;
        int seg = sb & 63, b = sb >> 6;
        int w = t >> 5, lane = t & 31;
        int pix = seg * 256 + t;
        int sel = d_sel[b * HW + pix];
        int r1 = sel & 7, r2 = sel >> 3;

        int rank1 = 0, rank2 = 0;
        unsigned ltm = (1u << lane) - 1u;
        #pragma unroll
        for (int r = 0; r < Rr; r++) {
            unsigned m = __ballot_sync(0xFFFFFFFFu, (r1 == r) || (r2 == r));
            if (lane == 0) wcnt[w][r] = __popc(m);
            if (r1 == r) rank1 = __popc(m & ltm);
            if (r2 == r) rank2 = __popc(m & ltm);
        }
        __syncthreads();
        int wb1 = 0, wb2 = 0;
        for (int w2i = 0; w2i < w; w2i++) { wb1 += wcnt[w2i][r1]; wb2 += wcnt[w2i][r2]; }

        unsigned short pv = (unsigned short)pix;
        if (r1 == r2) {
            int off = d_segbase[(b * Rr + r1) * 64 + seg] + wb1 + rank1;
            d_list[(b * Rr + r1) * HW + off] = (unsigned short)(pv | (3u << 14));
        } else {
            int off1 = d_segbase[(b * Rr + r1) * 64 + seg] + wb1 + rank1;
            d_list[(b * Rr + r1) * HW + off1] = (unsigned short)(pv | (1u << 14));
            int off2 = d_segbase[(b * Rr + r2) * 64 + seg] + wb2 + rank2;
            d_list[(b * Rr + r2) * HW + off2] = (unsigned short)(pv | (2u << 14));
        }
    }
}

// ================= L4: dynconv (R10 core; epilogue -> [pix][ch] float4 stores) =================
__global__ void __launch_bounds__(256) dynconv_kernel(const float* __restrict__ in) {
    int b = blockIdx.z, r = blockIdx.y;
    int cnt = d_cnt[b * Rr + r];
    int base = blockIdx.x * 512;
    if (base >= cnt) return;

    __shared__ __align__(16) float ks[288 * 32];   // [c*9+tap][oo]
    {
        const float4* kg = (const float4*)(d_kern + (size_t)(b * Rr + r) * 9216);
        float4* kd = (float4*)ks;
        #pragma unroll
        for (int i = 0; i < 9; i++) kd[threadIdx.x + 256 * i] = kg[threadIdx.x + 256 * i];
    }
    __syncthreads();

    int w = threadIdx.x >> 5, lane = threadIdx.x & 31;
    const unsigned short* lst = d_list + (b * Rr + r) * HW;
    const float* inb = in + (size_t)b * Cc * HW;

    int e0 = base + w * 64 + lane;
    int e1 = e0 + 32;
    int ent0 = (e0 < cnt) ? (int)lst[e0] : 0;
    int ent1 = (e1 < cnt) ? (int)lst[e1] : 0;
    int f0 = (e0 < cnt) ? (ent0 >> 14) : 0;
    int f1 = (e1 < cnt) ? (ent1 >> 14) : 0;
    int pix0 = ent0 & 0x3FFF, pix1 = ent1 & 0x3FFF;
    int y0 = pix0 >> 7, x0 = pix0 & 127;
    int y1 = pix1 >> 7, x1 = pix1 & 127;

    unsigned vm0 = 0, vm1 = 0;
    #pragma unroll
    for (int tap = 0; tap < 9; tap++) {
        int ky = tap / 3, kx = tap % 3;
        if ((unsigned)(y0 + ky - 1) < 128u && (unsigned)(x0 + kx - 1) < 128u) vm0 |= 1u << tap;
        if ((unsigned)(y1 + ky - 1) < 128u && (unsigned)(x1 + kx - 1) < 128u) vm1 |= 1u << tap;
    }
    if (f0 == 0) vm0 = 0;
    if (f1 == 0) vm1 = 0;

    const int DOFF[9] = {-Ww - 1, -Ww, -Ww + 1, -1, 0, 1, Ww - 1, Ww, Ww + 1};

    ull acc0[16], acc1[16];
    #pragma unroll
    for (int u = 0; u < 16; u++) { acc0[u] = 0; acc1[u] = 0; }

    for (int c = 0; c < Cc; c++) {
        const float* inc = inb + (size_t)c * HW;
        const float* kc = ks + c * 288;
        #pragma unroll
        for (int tap = 0; tap < 9; tap++) {
            float v0 = (vm0 >> tap & 1) ? __ldg(inc + pix0 + DOFF[tap]) : 0.f;
            float v1 = (vm1 >> tap & 1) ? __ldg(inc + pix1 + DOFF[tap]) : 0.f;
            ull a0 = pack2(v0), a1 = pack2(v1);
            const ulonglong2* wp = (const ulonglong2*)(kc + tap * 32);
            #pragma unroll
            for (int q = 0; q < 8; q++) {
                ulonglong2 wq = wp[q];
                acc0[q * 2]     = ffma2(a0, wq.x, acc0[q * 2]);
                acc0[q * 2 + 1] = ffma2(a0, wq.y, acc0[q * 2 + 1]);
                acc1[q * 2]     = ffma2(a1, wq.x, acc1[q * 2]);
                acc1[q * 2 + 1] = ffma2(a1, wq.y, acc1[q * 2 + 1]);
            }
        }
    }

    float* catb = d_cat + (size_t)b * HW * 64;
    const float* a0f = (const float*)acc0;
    const float* a1f = (const float*)acc1;
    float* cp0 = catb + (size_t)pix0 * 64;
    float* cp1 = catb + (size_t)pix1 * 64;
    if (f0 & 1) {
        #pragma unroll
        for (int q = 0; q < 8; q++)
            ((float4*)cp0)[q] = make_float4(a0f[4*q], a0f[4*q+1], a0f[4*q+2], a0f[4*q+3]);
    }
    if (f0 & 2) {
        #pragma unroll
        for (int q = 0; q < 8; q++)
            ((float4*)(cp0 + 32))[q] = make_float4(a0f[4*q], a0f[4*q+1], a0f[4*q+2], a0f[4*q+3]);
    }
    if (f1 & 1) {
        #pragma unroll
        for (int q = 0; q < 8; q++)
            ((float4*)cp1)[q] = make_float4(a1f[4*q], a1f[4*q+1], a1f[4*q+2], a1f[4*q+3]);
    }
    if (f1 & 2) {
        #pragma unroll
        for (int q = 0; q < 8; q++)
            ((float4*)(cp1 + 32))[q] = make_float4(a1f[4*q], a1f[4*q+1], a1f[4*q+2], a1f[4*q+3]);
    }
}

// ================= L5: fusion via mma.sync bf16 (3-product split) =================
// grid (128 y, 16 b), block 256 (8 warps; warp = 16-px m-tile). K = 64ch x 9taps.
// smem: A_hi/A_lo 130x64 bf16 (SW128-swizzled), B_hi/B_lo 32x64 bf16.
#define FA_BYTES 16640
#define FB_BYTES 4096
#define F_SMEM (2 * FA_BYTES + 2 * FB_BYTES)   // 41472

__global__ void __launch_bounds__(256) fusion_mma_kernel(
    const float* __restrict__ in, const float* __restrict__ b_f,
    float* __restrict__ out) {
    extern __shared__ __align__(16) char sm[];
    char* Ah = sm;
    char* Al = sm + FA_BYTES;
    char* Bh = sm + 2 * FA_BYTES;
    char* Bl = sm + 2 * FA_BYTES + FB_BYTES;
    uint32_t AhA = smem_u32(Ah), AlA = smem_u32(Al);
    uint32_t BhA = smem_u32(Bh), BlA = smem_u32(Bl);

    int tid = threadIdx.x, wid = tid >> 5, l = tid & 31;
    int g = l >> 2, tq = l & 3;
    int y = blockIdx.x, b = blockIdx.y;
    const float* catb = d_cat + (size_t)b * HW * 64;

    float acc[4][4];
    #pragma unroll
    for (int nt = 0; nt < 4; nt++)
        #pragma unroll
        for (int i = 0; i < 4; i++) acc[nt][i] = 0.f;

    for (int ky = 0; ky < 3; ky++) {
        int yy = y + ky - 1;
        if ((unsigned)yy >= 128u) continue;
        __syncthreads();
        // ---- stage A: rows rr=0..129 (sx=rr-1), 64 ch, hi/lo bf16, swizzled ----
        {
            const float4* srcb = (const float4*)(catb + ((size_t)yy * 128 - 1) * 64);
            #pragma unroll
            for (int i = 0; i < 9; i++) {
                int f = i * 256 + tid;
                if (f < 2080) {
                    int rr = f >> 4, c4 = f & 15;
                    int sx = rr - 1;
                    float4 v = make_float4(0.f, 0.f, 0.f, 0.f);
                    if ((unsigned)sx < 128u) v = __ldg(srcb + f);
                    uint32_t hx = prmt7632(__float_as_uint(v.x), __float_as_uint(v.y));
                    uint32_t hz = prmt7632(__float_as_uint(v.z), __float_as_uint(v.w));
                    float lx = v.x - __uint_as_float(__float_as_uint(v.x) & 0xFFFF0000u);
                    float ly = v.y - __uint_as_float(__float_as_uint(v.y) & 0xFFFF0000u);
                    float lz = v.z - __uint_as_float(__float_as_uint(v.z) & 0xFFFF0000u);
                    float lw = v.w - __uint_as_float(__float_as_uint(v.w) & 0xFFFF0000u);
                    __nv_bfloat162 p0 = __floats2bfloat162_rn(lx, ly);
                    __nv_bfloat162 p1 = __floats2bfloat162_rn(lz, lw);
                    uint32_t off = rr * 128 + ((((c4 >> 1)) ^ (rr & 7)) << 4) + (c4 & 1) * 8;
                    *(uint2*)(Ah + off) = make_uint2(hx, hz);
                    *(uint2*)(Al + off) = make_uint2(*(uint32_t*)&p0, *(uint32_t*)&p1);
                }
            }
        }
        for (int kx = 0; kx < 3; kx++) {
            int tap = ky * 3 + kx;
            __syncthreads();
            // ---- stage B[tap]: [oo][ch] bf16 hi/lo, swizzled ----
            {
                int oo = tid >> 3, u = tid & 7;
                uint4 sh = ((const uint4*)d_wfbh)[tap * 256 + tid];
                uint4 sl = ((const uint4*)d_wfbl)[tap * 256 + tid];
                uint32_t off = oo * 128 + ((u ^ (oo & 7)) << 4);
                *(uint4*)(Bh + off) = sh;
                *(uint4*)(Bl + off) = sl;
            }
            __syncthreads();

            // A-frag lane address (rows shifted by kx)
            int rra = wid * 16 + (l & 15) + kx;     // 0..129
            int kha = l >> 4;
            // B-frag lane address
            int nn = ((l >> 4) & 1) * 8 + (l & 7);
            int khb = (l >> 3) & 1;

            #pragma unroll
            for (int kc = 0; kc < 4; kc++) {
                uint32_t ua = (uint32_t)(kc * 2 + kha);
                uint32_t aoff = rra * 128 + ((ua ^ (rra & 7)) << 4);
                uint32_t ah0, ah1, ah2, ah3, al0, al1, al2, al3;
                LDSM4(ah0, ah1, ah2, ah3, AhA + aoff);
                LDSM4(al0, al1, al2, al3, AlA + aoff);

                uint32_t ub = (uint32_t)(kc * 2 + khb);
                uint32_t boff1 = nn * 128 + ((ub ^ (nn & 7)) << 4);
                uint32_t boff2 = (nn + 16) * 128 + ((ub ^ ((nn + 16) & 7)) << 4);
                uint32_t bh0, bh1, bh2, bh3, bh4, bh5, bh6, bh7;
                uint32_t bl0, bl1, bl2, bl3, bl4, bl5, bl6, bl7;
                LDSM4(bh0, bh1, bh2, bh3, BhA + boff1);
                LDSM4(bh4, bh5, bh6, bh7, BhA + boff2);
                LDSM4(bl0, bl1, bl2, bl3, BlA + boff1);
                LDSM4(bl4, bl5, bl6, bl7, BlA + boff2);

                MMA16816(acc[0], ah0, ah1, ah2, ah3, bh0, bh1);
                MMA16816(acc[1], ah0, ah1, ah2, ah3, bh2, bh3);
                MMA16816(acc[2], ah0, ah1, ah2, ah3, bh4, bh5);
                MMA16816(acc[3], ah0, ah1, ah2, ah3, bh6, bh7);
                MMA16816(acc[0], ah0, ah1, ah2, ah3, bl0, bl1);
                MMA16816(acc[1], ah0, ah1, ah2, ah3, bl2, bl3);
                MMA16816(acc[2], ah0, ah1, ah2, ah3, bl4, bl5);
                MMA16816(acc[3], ah0, ah1, ah2, ah3, bl6, bl7);
                MMA16816(acc[0], al0, al1, al2, al3, bh0, bh1);
                MMA16816(acc[1], al0, al1, al2, al3, bh2, bh3);
                MMA16816(acc[2], al0, al1, al2, al3, bh4, bh5);
                MMA16816(acc[3], al0, al1, al2, al3, bh6, bh7);
            }
        }
    }

    // ---- epilogue: D (m16n8) lanes -> out + bias + residual ----
    int px0 = wid * 16 + g;
    size_t rowoff = (size_t)y * Ww;
    #pragma unroll
    for (int nt = 0; nt < 4; nt++) {
        int o0 = nt * 8 + tq * 2;
        float bi0 = __ldg(b_f + o0), bi1 = __ldg(b_f + o0 + 1);
        size_t i00 = ((size_t)(b * OUTC + o0)) * HW + rowoff + px0;
        size_t i01 = ((size_t)(b * OUTC + o0 + 1)) * HW + rowoff + px0;
        out[i00]     = acc[nt][0] + bi0 + __ldg(in + i00);
        out[i01]     = acc[nt][1] + bi1 + __ldg(in + i01);
        out[i00 + 8] = acc[nt][2] + bi0 + __ldg(in + i00 + 8);
        out[i01 + 8] = acc[nt][3] + bi1 + __ldg(in + i01 + 8);
    }
}

// ---------------- launch ----------------
extern "C" void kernel_launch(void* const* d_in, const int* in_sizes, int n_in,
                              void* d_out, int out_size) {
    const float* input  = (const float*)d_in[0];
    const float* guide  = (const float*)d_in[1];
    const float* w1     = (const float*)d_in[2];
    const float* b1     = (const float*)d_in[3];
    const float* w2     = (const float*)d_in[4];
    const float* b2     = (const float*)d_in[5];
    const float* w_spa  = (const float*)d_in[6];
    const float* b_spa  = (const float*)d_in[7];
    const float* w_spec = (const float*)d_in[8];
    const float* b_spec = (const float*)d_in[9];
    const float* w_f    = (const float*)d_in[10];
    const float* b_f    = (const float*)d_in[11];
    float* out = (float*)d_out;

    l1_kernel<<<L1_POOL + L1_S1 + L1_WFT, 256>>>(input, guide, w_spa, b_spa, w_spec, b_spec, w_f);
    l2_kernel<<<Bb + 1, 256>>>(w1, b1);
    l3_kernel<<<L3_KERN + 1024, 256>>>(w2, b2);
    dynconv_kernel<<<dim3(32, Rr, Bb), 256>>>(input);
    fusion_mma_kernel<<<dim3(Hh, Bb), 256, F_SMEM>>>(input, b_f, out);
}